// round 14
// baseline (speedup 1.0000x reference)
#include <cuda_runtime.h>
#include <cuda_fp16.h>
#include <cstdint>

#define BB 16
#define NN 4096
#define MM 1024
#define P0 (BB*MM*32)
#define P1 (BB*MM*64)
#define OUT_OFS (BB*3*MM)
#define GCOUNT (BB*MM)

__device__ int      g_samp[BB*MM];
__device__ int      g_idx0[P0];
__device__ int      g_idx1[P1];
__device__ __half   g_bufA[64*P1];
__device__ __half   g_bufB[96*P1];
__device__ __half   g_fth[BB*NN*64];
__device__ float    g_s[128];
__device__ float    g_t[128];
__device__ float    g_ps [128*4096];
__device__ float    g_ps2[128*4096];
__device__ float    g_pmax[128*GCOUNT];
__device__ float    g_pmin[128*GCOUNT];
__device__ uint16_t g_wth[6*12288];
__device__ uint16_t g_wtl[6*12288];

struct WPtrs { const float* w[6]; };

__device__ __forceinline__ uint32_t smem_u32(const void* p) {
    uint32_t a;
    asm("{ .reg .u64 t; cvta.to.shared.u64 t, %1; cvt.u32.u64 %0, t; }" : "=r"(a) : "l"(p));
    return a;
}
#define LDSMX4(r, addr) \
    asm volatile("ldmatrix.sync.aligned.m8n8.x4.shared.b16 {%0,%1,%2,%3}, [%4];" \
        : "=r"((r)[0]), "=r"((r)[1]), "=r"((r)[2]), "=r"((r)[3]) : "r"(addr))
#define MMAH(c, a, b0v, b1v) \
    asm volatile("mma.sync.aligned.m16n8k16.row.col.f32.f16.f16.f32 " \
        "{%0,%1,%2,%3}, {%4,%5,%6,%7}, {%8,%9}, {%0,%1,%2,%3};" \
        : "+f"((c)[0]), "+f"((c)[1]), "+f"((c)[2]), "+f"((c)[3]) \
        : "r"((a)[0]), "r"((a)[1]), "r"((a)[2]), "r"((a)[3]), "r"(b0v), "r"(b1v))

// ---------------- feature transpose -> fp16 (B,N,64) ----------------
__global__ __launch_bounds__(256) void ftr_kernel(const float* __restrict__ feat,
                                                  __half* __restrict__ fth)
{
    __shared__ float tile[32][33];
    int b = blockIdx.z, c0 = blockIdx.y*32, n0 = blockIdx.x*32;
    int tx = threadIdx.x, ty = threadIdx.y;
#pragma unroll
    for (int k = 0; k < 4; k++)
        tile[ty + k*8][tx] = feat[(size_t)(b*64 + c0 + ty + k*8)*NN + n0 + tx];
    __syncthreads();
#pragma unroll
    for (int k = 0; k < 4; k++)
        fth[((size_t)b*NN + n0 + ty + k*8)*64 + c0 + tx] = __float2half_rn(tile[tx][ty + k*8]);
}

// ---------------- FPS (blocks 0..15) + weight split (blocks 16..21) ----------------
__global__ __launch_bounds__(512) void fps_kernel(const float* __restrict__ pc,
                                                  int* __restrict__ samp,
                                                  float* __restrict__ dout,
                                                  WPtrs wp,
                                                  uint16_t* __restrict__ wth,
                                                  uint16_t* __restrict__ wtl)
{
    if (blockIdx.x >= BB) {
        const int cins[6]  = {67, 64, 64, 67, 64, 96};
        const int cpads[6] = {80, 64, 64, 80, 64, 96};
        const int couts[6] = {64, 64, 128, 64, 96, 128};
        const int gat[6]   = {1, 0, 0, 1, 0, 0};
        int l = blockIdx.x - BB;
        const float* W = wp.w[l];
        int cin = cins[l], cpad = cpads[l], cout = couts[l];
        for (int e = threadIdx.x; e < cout*cpad; e += 512) {
            int o = e / cpad, c = e - o*cpad;
            int src;
            if (gat[l]) src = (c < 64) ? c + 3 : (c < 67 ? c - 64 : -1);
            else        src = (c < cin) ? c : -1;
            float wf = (src >= 0) ? W[o*cin + src] : 0.0f;
            __half h = __float2half_rn(wf);
            __half lo = __float2half_rn(wf - __half2float(h));
            wth[l*12288 + e] = *reinterpret_cast<uint16_t*>(&h);
            wtl[l*12288 + e] = *reinterpret_cast<uint16_t*>(&lo);
        }
        return;
    }
    int b = blockIdx.x, tid = threadIdx.x;
    const float* px = pc + (size_t)b*3*NN;
    const float* py = px + NN;
    const float* pz = py + NN;
    float x[8], yv[8], z[8], dmin[8];
#pragma unroll
    for (int j = 0; j < 8; j++) {
        int i = tid + j*512;
        x[j] = px[i]; yv[j] = py[i]; z[j] = pz[i]; dmin[j] = 1e10f;
    }
    __shared__ unsigned svu[2][16], siu[2][16];
    int lane = tid & 31, w = tid >> 5, far = 0;
    for (int it = 0; it < MM; it++) {
        int buf = it & 1;
        if (tid == 0) {
            samp[b*MM + it] = far;
            dout[(b*3+0)*MM + it] = px[far];
            dout[(b*3+1)*MM + it] = py[far];
            dout[(b*3+2)*MM + it] = pz[far];
        }
        float cx = px[far], cy = py[far], cz = pz[far];
        float bv = -1.0f; int bi = 0;
#pragma unroll
        for (int j = 0; j < 8; j++) {
            float dx = x[j]-cx, dy = yv[j]-cy, dz = z[j]-cz;
            float d = __fadd_rn(__fadd_rn(__fmul_rn(dx,dx), __fmul_rn(dy,dy)), __fmul_rn(dz,dz));
            float nd = fminf(dmin[j], d);
            dmin[j] = nd;
            if (nd > bv) { bv = nd; bi = tid + j*512; }
        }
        unsigned fb = __float_as_uint(bv);
        unsigned mw = __reduce_max_sync(0xffffffffu, fb);
        unsigned mi = __reduce_min_sync(0xffffffffu, (fb == mw) ? (unsigned)bi : 0xffffffffu);
        if (lane == 0) { svu[buf][w] = mw; siu[buf][w] = mi; }
        __syncthreads();
        unsigned f2 = (lane < 16) ? svu[buf][lane] : 0u;
        unsigned i2 = (lane < 16) ? siu[buf][lane] : 0xffffffffu;
        unsigned m2 = __reduce_max_sync(0xffffffffu, f2);
        far = (int)__reduce_min_sync(0xffffffffu, (f2 == m2) ? i2 : 0xffffffffu);
    }
}

// ---------------- dual-radius ball query, phase-split ----------------
__global__ __launch_bounds__(256) void ballquery2_kernel(const float* __restrict__ pc,
    const int* __restrict__ samp, int* __restrict__ gidx0, int* __restrict__ gidx1,
    float r2a, float r2b)
{
    extern __shared__ float sh[];
    float* sx = sh; float* sy = sh + NN; float* sz = sh + 2*NN;
    int b = blockIdx.x;
    const float* px = pc + (size_t)b*3*NN;
    for (int i = threadIdx.x; i < NN; i += blockDim.x) {
        sx[i] = px[i]; sy[i] = px[NN+i]; sz[i] = px[2*NN+i];
    }
    __syncthreads();
    int lane = threadIdx.x & 31, wid = threadIdx.x >> 5;
    int mstart = blockIdx.y * 32;
    unsigned lt = (1u << lane) - 1u;
    for (int m = mstart + wid; m < mstart + 32; m += 8) {
        int ci = samp[b*MM + m];
        float cx = sx[ci], cy = sy[ci], cz = sz[ci];
        int cnt0 = 0, cnt1 = 0, f0 = -1, f1 = -1;
        int* out0 = gidx0 + ((size_t)(b*MM + m))*32;
        int* out1 = gidx1 + ((size_t)(b*MM + m))*64;
        int base = 0;
        // phase 1: both radii until K1 fills
        for (; base < NN && cnt1 < 64; base += 32) {
            int i = base + lane;
            float dx = sx[i]-cx, dy = sy[i]-cy, dz = sz[i]-cz;
            float d = __fadd_rn(__fadd_rn(__fmul_rn(dx,dx), __fmul_rn(dy,dy)), __fmul_rn(dz,dz));
            bool ok0 = d < r2a, ok1 = d < r2b;
            unsigned m0 = __ballot_sync(0xffffffffu, ok0);
            unsigned m1 = __ballot_sync(0xffffffffu, ok1);
            if (f0 < 0 && m0) f0 = base + __ffs(m0) - 1;
            if (f1 < 0 && m1) f1 = base + __ffs(m1) - 1;
            int p0 = cnt0 + __popc(m0 & lt);
            int p1 = cnt1 + __popc(m1 & lt);
            if (ok0 && p0 < 32) out0[p0] = i;
            if (ok1 && p1 < 64) out1[p1] = i;
            cnt0 = min(32, cnt0 + __popc(m0));
            cnt1 = min(64, cnt1 + __popc(m1));
        }
        // phase 2: small radius only
        for (; base < NN && cnt0 < 32; base += 32) {
            int i = base + lane;
            float dx = sx[i]-cx, dy = sy[i]-cy, dz = sz[i]-cz;
            float d = __fadd_rn(__fadd_rn(__fmul_rn(dx,dx), __fmul_rn(dy,dy)), __fmul_rn(dz,dz));
            bool ok0 = d < r2a;
            unsigned m0 = __ballot_sync(0xffffffffu, ok0);
            if (f0 < 0 && m0) f0 = base + __ffs(m0) - 1;
            int p0 = cnt0 + __popc(m0 & lt);
            if (ok0 && p0 < 32) out0[p0] = i;
            cnt0 = min(32, cnt0 + __popc(m0));
        }
        for (int p = cnt0 + lane; p < 32; p += 32) out0[p] = f0;
        for (int p = cnt1 + lane; p < 64; p += 32) out1[p] = f1;
    }
}

// ---------------- tensor-core conv: 512 pos (4 M-tiles/warp) x C per block ----------------
template<bool GATHER, bool POOL, int C, int CPAD, int KP>
__global__ __launch_bounds__(256, 1) void conv_mma(
    const __half* __restrict__ xin,
    const uint16_t* __restrict__ Whi, const uint16_t* __restrict__ Wlo,
    const float* __restrict__ bias,
    const float* __restrict__ bns, const float* __restrict__ bnt,
    __half* __restrict__ y, float* __restrict__ ps, float* __restrict__ ps2,
    float* __restrict__ pmax, float* __restrict__ pmin,
    int cstride,
    const float* __restrict__ pc, const __half* __restrict__ fth,
    const float* __restrict__ newpc, const int* __restrict__ gidx,
    int mkshift, int kshift)
{
    constexpr int NK = CPAD/16;
    constexpr int WSTR = CPAD*2 + 16;
    constexpr int XROW = 48, XPLANE = 512*XROW;     // 24576
    constexpr int WOFF = 2*XPLANE;
    constexpr int MOFF = WOFF + 2*C*WSTR;

    extern __shared__ __align__(16) unsigned char smem[];
    __half2* ss2 = (__half2*)(smem + MOFF);
    __half2* st2 = (__half2*)(smem + MOFF + 512);
    unsigned* sfb = (unsigned*)(smem + MOFF + 1024);
    float* sdx = (float*)(smem + MOFF + 3072);
    float* sdy = (float*)(smem + MOFF + 5120);
    float* sdz = (float*)(smem + MOFF + 7168);
    float* sm1 = (float*)(smem + MOFF + 9216);
    float* sm2 = sm1 + 8*C;

    const int tid = threadIdx.x, lane = tid & 31, w = tid >> 5;
    const int pblock = blockIdx.x * 512;
    const int ocbase = blockIdx.y * C;
    const int nblk = gridDim.x;
    const uint16_t* Whi_b = Whi + (size_t)ocbase*CPAD;
    const uint16_t* Wlo_b = Wlo + (size_t)ocbase*CPAD;

    if (GATHER) {
        for (int e = tid; e < 512; e += 256) {
            int p = pblock + e;
            int bbv = p >> mkshift, mmv = (p >> kshift) & (MM-1);
            int ix = gidx[p];
            sfb[e] = (unsigned)((bbv*NN + ix) * 64);
            sdx[e] = pc[(size_t)(bbv*3+0)*NN+ix] - newpc[(size_t)(bbv*3+0)*MM+mmv];
            sdy[e] = pc[(size_t)(bbv*3+1)*NN+ix] - newpc[(size_t)(bbv*3+1)*MM+mmv];
            sdz[e] = pc[(size_t)(bbv*3+2)*NN+ix] - newpc[(size_t)(bbv*3+2)*MM+mmv];
        }
    } else {
        if (tid < CPAD/2) {
            ss2[tid] = __floats2half2_rn(bns[2*tid], bns[2*tid+1]);
            st2[tid] = __floats2half2_rn(bnt[2*tid], bnt[2*tid+1]);
        }
    }
    for (int e = tid; e < C*CPAD/2; e += 256) {
        int o = e / (CPAD/2), cp = e - o*(CPAD/2);
        *(uint32_t*)(smem + WOFF + o*WSTR + cp*4) = ((const uint32_t*)Whi_b)[e];
        *(uint32_t*)(smem + WOFF + C*WSTR + o*WSTR + cp*4) = ((const uint32_t*)Wlo_b)[e];
    }
    __syncthreads();

    uint2 hr[8];
    auto stage_load = [&](int kc) {
#pragma unroll
        for (int i = 0; i < 8; i++) {
            int e = tid + i*256, pos = e >> 2, c4 = e & 3;
            if (GATHER) {
                if (kc < 4) hr[i] = *(const uint2*)&fth[sfb[pos] + kc*16 + c4*4];
            } else {
                hr[i] = *(const uint2*)&xin[(size_t)(pblock+pos)*CPAD + kc*16 + c4*4];
            }
        }
    };
    auto stage_conv = [&](int kc, int buf) {
        unsigned char* xh = smem + buf*XPLANE;
#pragma unroll
        for (int i = 0; i < 8; i++) {
            int e = tid + i*256, pos = e >> 2, c4 = e & 3;
            uint2 o2v;
            if (GATHER) {
                if (kc < 4) o2v = hr[i];
                else if (c4 == 0) {
                    __half2 a = __floats2half2_rn(sdx[pos], sdy[pos]);
                    __half2 b = __floats2half2_rn(sdz[pos], 0.f);
                    o2v = make_uint2(*(uint32_t*)&a, *(uint32_t*)&b);
                } else o2v = make_uint2(0u, 0u);
            } else {
                int h0 = (kc*16 + c4*4) >> 1;
                __half2 v0 = *(__half2*)&hr[i].x;
                __half2 v1 = *(__half2*)&hr[i].y;
                v0 = __hfma2_relu(v0, ss2[h0],   st2[h0]);
                v1 = __hfma2_relu(v1, ss2[h0+1], st2[h0+1]);
                o2v = make_uint2(*(uint32_t*)&v0, *(uint32_t*)&v1);
            }
            *(uint2*)(xh + pos*XROW + c4*8) = o2v;
        }
    };

    const uint32_t base = smem_u32(smem);
    const uint32_t aoff = base + (uint32_t)((w*64 + (lane & 15))*XROW + (lane >> 4)*16);
    const uint32_t boff = base + WOFF +
        (uint32_t)((((lane >> 4) & 1)*8 + (lane & 7))*WSTR + ((lane >> 3) & 1)*16);

    float acc[4][C/8][4];
#pragma unroll
    for (int t = 0; t < 4; t++)
#pragma unroll
        for (int n = 0; n < C/8; n++)
#pragma unroll
            for (int c = 0; c < 4; c++) acc[t][n][c] = 0.f;

    stage_load(0); stage_conv(0, 0);
    __syncthreads();

    for (int kc = 0; kc < NK; kc++) {
        int buf = kc & 1;
        if (kc + 1 < NK) stage_load(kc + 1);
        uint32_t bh[C/16][4], bl[C/16][4];
#pragma unroll
        for (int j = 0; j < C/16; j++) {
            LDSMX4(bh[j], boff + j*16*WSTR + kc*32);
            LDSMX4(bl[j], boff + C*WSTR + j*16*WSTR + kc*32);
        }
#pragma unroll
        for (int t = 0; t < 4; t++) {
            uint32_t ah[4];
            LDSMX4(ah, aoff + t*16*XROW + buf*XPLANE);
#pragma unroll
            for (int j = 0; j < C/16; j++) {
                MMAH(acc[t][2*j],   ah, bh[j][0], bh[j][1]);
                MMAH(acc[t][2*j+1], ah, bh[j][2], bh[j][3]);
            }
#pragma unroll
            for (int j = 0; j < C/16; j++) {
                MMAH(acc[t][2*j],   ah, bl[j][0], bl[j][1]);
                MMAH(acc[t][2*j+1], ah, bl[j][2], bl[j][3]);
            }
        }
        if (kc + 1 < NK) stage_conv(kc + 1, buf ^ 1);
        __syncthreads();
    }

    const int q = lane >> 2, r2i = (lane & 3)*2;
#pragma unroll
    for (int nt = 0; nt < C/8; nt++) {
        int ocl = nt*8 + r2i;
        int oc  = ocbase + ocl;
        float2 bv = *(const float2*)&bias[oc];
        float s1x = 0.f, s1y = 0.f, s2x = 0.f, s2y = 0.f;
        float mxAx = -1e30f, mxAy = -1e30f, mnAx = 1e30f, mnAy = 1e30f;
        float mxBx = -1e30f, mxBy = -1e30f, mnBx = 1e30f, mnBy = 1e30f;
#pragma unroll
        for (int t = 0; t < 4; t++) {
            float2 c01 = make_float2(acc[t][nt][0]+bv.x, acc[t][nt][1]+bv.y);
            float2 c23 = make_float2(acc[t][nt][2]+bv.x, acc[t][nt][3]+bv.y);
            if (!POOL) {
                __half2 h01 = __floats2half2_rn(c01.x, c01.y);
                __half2 h23 = __floats2half2_rn(c23.x, c23.y);
                *(__half2*)&y[(size_t)(pblock + w*64 + t*16 + q)*cstride + oc]     = h01;
                *(__half2*)&y[(size_t)(pblock + w*64 + t*16 + q + 8)*cstride + oc] = h23;
                c01 = __half22float2(h01);
                c23 = __half22float2(h23);
            }
            s1x += c01.x + c23.x;  s1y += c01.y + c23.y;
            s2x += c01.x*c01.x + c23.x*c23.x;
            s2y += c01.y*c01.y + c23.y*c23.y;
            if (POOL) {
                if (t < 2) {
                    mxAx = fmaxf(mxAx, fmaxf(c01.x, c23.x)); mxAy = fmaxf(mxAy, fmaxf(c01.y, c23.y));
                    mnAx = fminf(mnAx, fminf(c01.x, c23.x)); mnAy = fminf(mnAy, fminf(c01.y, c23.y));
                } else {
                    mxBx = fmaxf(mxBx, fmaxf(c01.x, c23.x)); mxBy = fmaxf(mxBy, fmaxf(c01.y, c23.y));
                    mnBx = fminf(mnBx, fminf(c01.x, c23.x)); mnBy = fminf(mnBy, fminf(c01.y, c23.y));
                }
            }
        }
        if (POOL && KP == 64) {   // one group per warp: combine halves
            mxAx = fmaxf(mxAx, mxBx); mxAy = fmaxf(mxAy, mxBy);
            mnAx = fminf(mnAx, mnBx); mnAy = fminf(mnAy, mnBy);
        }
#pragma unroll
        for (int o2 = 4; o2 <= 16; o2 <<= 1) {
            s1x += __shfl_xor_sync(0xffffffffu, s1x, o2);
            s1y += __shfl_xor_sync(0xffffffffu, s1y, o2);
            s2x += __shfl_xor_sync(0xffffffffu, s2x, o2);
            s2y += __shfl_xor_sync(0xffffffffu, s2y, o2);
            if (POOL) {
                mxAx = fmaxf(mxAx, __shfl_xor_sync(0xffffffffu, mxAx, o2));
                mxAy = fmaxf(mxAy, __shfl_xor_sync(0xffffffffu, mxAy, o2));
                mnAx = fminf(mnAx, __shfl_xor_sync(0xffffffffu, mnAx, o2));
                mnAy = fminf(mnAy, __shfl_xor_sync(0xffffffffu, mnAy, o2));
                if (KP == 32) {
                    mxBx = fmaxf(mxBx, __shfl_xor_sync(0xffffffffu, mxBx, o2));
                    mxBy = fmaxf(mxBy, __shfl_xor_sync(0xffffffffu, mxBy, o2));
                    mnBx = fminf(mnBx, __shfl_xor_sync(0xffffffffu, mnBx, o2));
                    mnBy = fminf(mnBy, __shfl_xor_sync(0xffffffffu, mnBy, o2));
                }
            }
        }
        if (q == 0) {
            sm1[w*C + ocl] = s1x; sm1[w*C + ocl + 1] = s1y;
            sm2[w*C + ocl] = s2x; sm2[w*C + ocl + 1] = s2y;
            if (POOL) {
                if (KP == 32) {
                    size_t g = (size_t)(pblock >> 5) + w*2;
                    pmax[(size_t)oc*GCOUNT + g] = mxAx; pmax[(size_t)(oc+1)*GCOUNT + g] = mxAy;
                    pmin[(size_t)oc*GCOUNT + g] = mnAx; pmin[(size_t)(oc+1)*GCOUNT + g] = mnAy;
                    pmax[(size_t)oc*GCOUNT + g+1] = mxBx; pmax[(size_t)(oc+1)*GCOUNT + g+1] = mxBy;
                    pmin[(size_t)oc*GCOUNT + g+1] = mnBx; pmin[(size_t)(oc+1)*GCOUNT + g+1] = mnBy;
                } else {
                    size_t g = (size_t)(pblock >> 6) + w;
                    pmax[(size_t)oc*GCOUNT + g] = mxAx; pmax[(size_t)(oc+1)*GCOUNT + g] = mxAy;
                    pmin[(size_t)oc*GCOUNT + g] = mnAx; pmin[(size_t)(oc+1)*GCOUNT + g] = mnAy;
                }
            }
        }
    }
    __syncthreads();
    for (int e = tid; e < C; e += 256) {
        float a = 0.f, b2 = 0.f;
#pragma unroll
        for (int wi = 0; wi < 8; wi++) { a += sm1[wi*C + e]; b2 += sm2[wi*C + e]; }
        ps [(size_t)(ocbase + e)*nblk + blockIdx.x] = a;
        ps2[(size_t)(ocbase + e)*nblk + blockIdx.x] = b2;
    }
}

// ---------------- finalize BN ----------------
__global__ __launch_bounds__(256) void finalize_kernel(const float* __restrict__ ps,
    const float* __restrict__ ps2, int nblk, float invP,
    const float* __restrict__ gamma, const float* __restrict__ beta,
    float* __restrict__ s, float* __restrict__ t)
{
    int c = blockIdx.x;
    float a = 0.f, b = 0.f;
    for (int i = threadIdx.x; i < nblk; i += 256) {
        a += ps [(size_t)c*nblk + i];
        b += ps2[(size_t)c*nblk + i];
    }
#pragma unroll
    for (int off = 16; off > 0; off >>= 1) {
        a += __shfl_down_sync(0xffffffffu, a, off);
        b += __shfl_down_sync(0xffffffffu, b, off);
    }
    __shared__ float sa[8], sb[8];
    int lane = threadIdx.x & 31, w = threadIdx.x >> 5;
    if (lane == 0) { sa[w] = a; sb[w] = b; }
    __syncthreads();
    if (threadIdx.x < 8) {
        a = sa[threadIdx.x]; b = sb[threadIdx.x];
#pragma unroll
        for (int off = 4; off > 0; off >>= 1) {
            a += __shfl_down_sync(0xffu, a, off);
            b += __shfl_down_sync(0xffu, b, off);
        }
        if (threadIdx.x == 0) {
            float mu = a * invP;
            float var = b * invP - mu*mu;
            float sc = gamma[c] / sqrtf(var + 1e-5f);
            s[c] = sc;
            t[c] = beta[c] - mu * sc;
        }
    }
}

// ---------------- pool apply ----------------
__global__ __launch_bounds__(256) void pool_apply_kernel(const float* __restrict__ pmax,
    const float* __restrict__ pmin, const float* __restrict__ s, const float* __restrict__ t,
    float* __restrict__ out, int chbase)
{
    int gid = blockIdx.x*256 + threadIdx.x;
    int oc = gid >> 14, g = gid & 16383;
    float sc = s[oc], tc = t[oc];
    float v = (sc > 0.f) ? pmax[gid] : pmin[gid];
    float r = fmaxf(v*sc + tc, 0.f);
    out[OUT_OFS + ((size_t)((g >> 10)*256 + chbase + oc))*MM + (g & 1023)] = r;
}

// ---------------- host ----------------
extern "C" void kernel_launch(void* const* d_in, const int* in_sizes, int n_in,
                              void* d_out, int out_size)
{
    const float* pc   = (const float*)d_in[0];
    const float* feat = (const float*)d_in[1];
    const float *bp[6], *gp[6], *bep[6];
    WPtrs wargs;
    for (int i = 0; i < 6; i++) {
        wargs.w[i] = (const float*)d_in[2 + 4*i];
        bp[i]  = (const float*)d_in[3 + 4*i];
        gp[i]  = (const float*)d_in[4 + 4*i];
        bep[i] = (const float*)d_in[5 + 4*i];
    }
    float* out = (float*)d_out;

    int *samp, *idx0, *idx1;
    float *sv, *tv, *ps, *ps2, *pmax, *pmin;
    __half *bufA, *bufB, *fth;
    uint16_t *wth, *wtl;
    cudaGetSymbolAddress((void**)&samp, g_samp);
    cudaGetSymbolAddress((void**)&idx0, g_idx0);
    cudaGetSymbolAddress((void**)&idx1, g_idx1);
    cudaGetSymbolAddress((void**)&bufA, g_bufA);
    cudaGetSymbolAddress((void**)&bufB, g_bufB);
    cudaGetSymbolAddress((void**)&fth,  g_fth);
    cudaGetSymbolAddress((void**)&sv,   g_s);
    cudaGetSymbolAddress((void**)&tv,   g_t);
    cudaGetSymbolAddress((void**)&ps,   g_ps);
    cudaGetSymbolAddress((void**)&ps2,  g_ps2);
    cudaGetSymbolAddress((void**)&pmax, g_pmax);
    cudaGetSymbolAddress((void**)&pmin, g_pmin);
    cudaGetSymbolAddress((void**)&wth,  g_wth);
    cudaGetSymbolAddress((void**)&wtl,  g_wtl);

    // smem = 49152 (X) + 2*C*WSTR (W) + 9216 + 2*8*C*4 (stats)
    const int sm_A = 49152 + 2*64*176 + 9216 + 4096;   // gather C64 CPAD80 = 84992
    const int sm_B = 49152 + 2*64*144 + 9216 + 4096;   // C64 CPAD64      = 80896
    const int sm_D = 49152 + 2*48*144 + 9216 + 3072;   // C48 CPAD64      = 75264
    const int sm_E = 49152 + 2*64*208 + 9216 + 4096;   // C64 CPAD96 pool = 89088
    cudaFuncSetAttribute(conv_mma<true,false,64,80,32>,  cudaFuncAttributeMaxDynamicSharedMemorySize, sm_A);
    cudaFuncSetAttribute(conv_mma<false,false,64,64,32>, cudaFuncAttributeMaxDynamicSharedMemorySize, sm_B);
    cudaFuncSetAttribute(conv_mma<false,true,64,64,32>,  cudaFuncAttributeMaxDynamicSharedMemorySize, sm_B);
    cudaFuncSetAttribute(conv_mma<false,false,48,64,32>, cudaFuncAttributeMaxDynamicSharedMemorySize, sm_D);
    cudaFuncSetAttribute(conv_mma<false,true,64,96,64>,  cudaFuncAttributeMaxDynamicSharedMemorySize, sm_E);

    ftr_kernel<<<dim3(128, 2, BB), dim3(32, 8)>>>(feat, fth);
    fps_kernel<<<BB + 6, 512>>>(pc, samp, out, wargs, wth, wtl);
    ballquery2_kernel<<<dim3(BB,32), 256, 3*NN*sizeof(float)>>>(pc, samp, idx0, idx1, 0.01f, 0.04f);

    const int nb0 = P0/512, nb1 = P1/512;

    // branch 1 first (bigger): 67->64->96->128, K=64
    conv_mma<true,false,64,80,32><<<dim3(nb1,1), 256, sm_A>>>(nullptr, wth+3*12288, wtl+3*12288,
        bp[3], nullptr, nullptr, bufA, ps, ps2, nullptr, nullptr, 64, pc, fth, out, idx1, 16, 6);
    finalize_kernel<<<64, 256>>>(ps, ps2, nb1, 1.f/P1, gp[3], bep[3], sv, tv);
    conv_mma<false,false,48,64,32><<<dim3(nb1,2), 256, sm_D>>>(bufA, wth+4*12288, wtl+4*12288,
        bp[4], sv, tv, bufB, ps, ps2, nullptr, nullptr, 96, nullptr, nullptr, nullptr, nullptr, 0, 0);
    finalize_kernel<<<96, 256>>>(ps, ps2, nb1, 1.f/P1, gp[4], bep[4], sv, tv);
    conv_mma<false,true,64,96,64><<<dim3(nb1,2), 256, sm_E>>>(bufB, wth+5*12288, wtl+5*12288,
        bp[5], sv, tv, nullptr, ps, ps2, pmax, pmin, 128, nullptr, nullptr, nullptr, nullptr, 0, 0);
    finalize_kernel<<<128, 256>>>(ps, ps2, nb1, 1.f/P1, gp[5], bep[5], sv, tv);
    pool_apply_kernel<<<(128*GCOUNT)/256, 256>>>(pmax, pmin, sv, tv, out, 128);

    // branch 0: 67->64->64->128, K=32
    conv_mma<true,false,64,80,32><<<dim3(nb0,1), 256, sm_A>>>(nullptr, wth+0*12288, wtl+0*12288,
        bp[0], nullptr, nullptr, bufA, ps, ps2, nullptr, nullptr, 64, pc, fth, out, idx0, 15, 5);
    finalize_kernel<<<64, 256>>>(ps, ps2, nb0, 1.f/P0, gp[0], bep[0], sv, tv);
    conv_mma<false,false,64,64,32><<<dim3(nb0,1), 256, sm_B>>>(bufA, wth+1*12288, wtl+1*12288,
        bp[1], sv, tv, bufB, ps, ps2, nullptr, nullptr, 64, nullptr, nullptr, nullptr, nullptr, 0, 0);
    finalize_kernel<<<64, 256>>>(ps, ps2, nb0, 1.f/P0, gp[1], bep[1], sv, tv);
    conv_mma<false,true,64,64,32><<<dim3(nb0,2), 256, sm_B>>>(bufB, wth+2*12288, wtl+2*12288,
        bp[2], sv, tv, nullptr, ps, ps2, pmax, pmin, 128, nullptr, nullptr, nullptr, nullptr, 0, 0);
    finalize_kernel<<<128, 256>>>(ps, ps2, nb0, 1.f/P0, gp[2], bep[2], sv, tv);
    pool_apply_kernel<<<(128*GCOUNT)/256, 256>>>(pmax, pmin, sv, tv, out, 0);
}

// round 15
// speedup vs baseline: 1.1306x; 1.1306x over previous
#include <cuda_runtime.h>
#include <cuda_fp16.h>
#include <cstdint>

#define BB 16
#define NN 4096
#define MM 1024
#define P0 (BB*MM*32)
#define P1 (BB*MM*64)
#define OUT_OFS (BB*3*MM)
#define GCOUNT (BB*MM)

__device__ int      g_samp[BB*MM];
__device__ int      g_idx0[P0];
__device__ int      g_idx1[P1];
__device__ __half   g_bufA[64*P1];
__device__ __half   g_bufB[96*P1];
__device__ __half   g_fth[BB*NN*64];
__device__ float    g_s[128];
__device__ float    g_t[128];
__device__ float    g_ps [128*8192];
__device__ float    g_ps2[128*8192];
__device__ float    g_pmax[128*GCOUNT];
__device__ float    g_pmin[128*GCOUNT];
__device__ uint16_t g_wth[6*12288];

struct WPtrs { const float* w[6]; };

__device__ __forceinline__ uint32_t smem_u32(const void* p) {
    uint32_t a;
    asm("{ .reg .u64 t; cvta.to.shared.u64 t, %1; cvt.u32.u64 %0, t; }" : "=r"(a) : "l"(p));
    return a;
}
#define LDSMX4(r, addr) \
    asm volatile("ldmatrix.sync.aligned.m8n8.x4.shared.b16 {%0,%1,%2,%3}, [%4];" \
        : "=r"((r)[0]), "=r"((r)[1]), "=r"((r)[2]), "=r"((r)[3]) : "r"(addr))
#define MMAH(c, a, b0v, b1v) \
    asm volatile("mma.sync.aligned.m16n8k16.row.col.f32.f16.f16.f32 " \
        "{%0,%1,%2,%3}, {%4,%5,%6,%7}, {%8,%9}, {%0,%1,%2,%3};" \
        : "+f"((c)[0]), "+f"((c)[1]), "+f"((c)[2]), "+f"((c)[3]) \
        : "r"((a)[0]), "r"((a)[1]), "r"((a)[2]), "r"((a)[3]), "r"(b0v), "r"(b1v))

// ---------------- feature transpose -> fp16 (B,N,64) ----------------
__global__ __launch_bounds__(256) void ftr_kernel(const float* __restrict__ feat,
                                                  __half* __restrict__ fth)
{
    __shared__ float tile[32][33];
    int b = blockIdx.z, c0 = blockIdx.y*32, n0 = blockIdx.x*32;
    int tx = threadIdx.x, ty = threadIdx.y;
#pragma unroll
    for (int k = 0; k < 4; k++)
        tile[ty + k*8][tx] = feat[(size_t)(b*64 + c0 + ty + k*8)*NN + n0 + tx];
    __syncthreads();
#pragma unroll
    for (int k = 0; k < 4; k++)
        fth[((size_t)b*NN + n0 + ty + k*8)*64 + c0 + tx] = __float2half_rn(tile[tx][ty + k*8]);
}

// ---------------- FPS (blocks 0..15) + weight fp16 (blocks 16..21) ----------------
__global__ __launch_bounds__(512) void fps_kernel(const float* __restrict__ pc,
                                                  int* __restrict__ samp,
                                                  float* __restrict__ dout,
                                                  WPtrs wp,
                                                  uint16_t* __restrict__ wth)
{
    if (blockIdx.x >= BB) {
        const int cins[6]  = {67, 64, 64, 67, 64, 96};
        const int cpads[6] = {80, 64, 64, 80, 64, 96};
        const int couts[6] = {64, 64, 128, 64, 96, 128};
        const int gat[6]   = {1, 0, 0, 1, 0, 0};
        int l = blockIdx.x - BB;
        const float* W = wp.w[l];
        int cin = cins[l], cpad = cpads[l], cout = couts[l];
        for (int e = threadIdx.x; e < cout*cpad; e += 512) {
            int o = e / cpad, c = e - o*cpad;
            int src;
            if (gat[l]) src = (c < 64) ? c + 3 : (c < 67 ? c - 64 : -1);
            else        src = (c < cin) ? c : -1;
            float wf = (src >= 0) ? W[o*cin + src] : 0.0f;
            __half h = __float2half_rn(wf);
            wth[l*12288 + e] = *reinterpret_cast<uint16_t*>(&h);
        }
        return;
    }
    int b = blockIdx.x, tid = threadIdx.x;
    const float* px = pc + (size_t)b*3*NN;
    const float* py = px + NN;
    const float* pz = py + NN;
    float x[8], yv[8], z[8], dmin[8];
#pragma unroll
    for (int j = 0; j < 8; j++) {
        int i = tid + j*512;
        x[j] = px[i]; yv[j] = py[i]; z[j] = pz[i]; dmin[j] = 1e10f;
    }
    __shared__ unsigned svu[2][16], siu[2][16];
    int lane = tid & 31, w = tid >> 5, far = 0;
    for (int it = 0; it < MM; it++) {
        int buf = it & 1;
        if (tid == 0) {
            samp[b*MM + it] = far;
            dout[(b*3+0)*MM + it] = px[far];
            dout[(b*3+1)*MM + it] = py[far];
            dout[(b*3+2)*MM + it] = pz[far];
        }
        float cx = px[far], cy = py[far], cz = pz[far];
        float bv = -1.0f; int bi = 0;
#pragma unroll
        for (int j = 0; j < 8; j++) {
            float dx = x[j]-cx, dy = yv[j]-cy, dz = z[j]-cz;
            float d = __fadd_rn(__fadd_rn(__fmul_rn(dx,dx), __fmul_rn(dy,dy)), __fmul_rn(dz,dz));
            float nd = fminf(dmin[j], d);
            dmin[j] = nd;
            if (nd > bv) { bv = nd; bi = tid + j*512; }
        }
        unsigned fb = __float_as_uint(bv);
        unsigned mw = __reduce_max_sync(0xffffffffu, fb);
        unsigned mi = __reduce_min_sync(0xffffffffu, (fb == mw) ? (unsigned)bi : 0xffffffffu);
        if (lane == 0) { svu[buf][w] = mw; siu[buf][w] = mi; }
        __syncthreads();
        unsigned f2 = (lane < 16) ? svu[buf][lane] : 0u;
        unsigned i2 = (lane < 16) ? siu[buf][lane] : 0xffffffffu;
        unsigned m2 = __reduce_max_sync(0xffffffffu, f2);
        far = (int)__reduce_min_sync(0xffffffffu, (f2 == m2) ? i2 : 0xffffffffu);
    }
}

// ---------------- dual-radius ball query, phase-split ----------------
__global__ __launch_bounds__(256) void ballquery2_kernel(const float* __restrict__ pc,
    const int* __restrict__ samp, int* __restrict__ gidx0, int* __restrict__ gidx1,
    float r2a, float r2b)
{
    extern __shared__ float sh[];
    float* sx = sh; float* sy = sh + NN; float* sz = sh + 2*NN;
    int b = blockIdx.x;
    const float* px = pc + (size_t)b*3*NN;
    for (int i = threadIdx.x; i < NN; i += blockDim.x) {
        sx[i] = px[i]; sy[i] = px[NN+i]; sz[i] = px[2*NN+i];
    }
    __syncthreads();
    int lane = threadIdx.x & 31, wid = threadIdx.x >> 5;
    int mstart = blockIdx.y * 32;
    unsigned lt = (1u << lane) - 1u;
    for (int m = mstart + wid; m < mstart + 32; m += 8) {
        int ci = samp[b*MM + m];
        float cx = sx[ci], cy = sy[ci], cz = sz[ci];
        int cnt0 = 0, cnt1 = 0, f0 = -1, f1 = -1;
        int* out0 = gidx0 + ((size_t)(b*MM + m))*32;
        int* out1 = gidx1 + ((size_t)(b*MM + m))*64;
        int base = 0;
        for (; base < NN && cnt1 < 64; base += 32) {
            int i = base + lane;
            float dx = sx[i]-cx, dy = sy[i]-cy, dz = sz[i]-cz;
            float d = __fadd_rn(__fadd_rn(__fmul_rn(dx,dx), __fmul_rn(dy,dy)), __fmul_rn(dz,dz));
            bool ok0 = d < r2a, ok1 = d < r2b;
            unsigned m0 = __ballot_sync(0xffffffffu, ok0);
            unsigned m1 = __ballot_sync(0xffffffffu, ok1);
            if (f0 < 0 && m0) f0 = base + __ffs(m0) - 1;
            if (f1 < 0 && m1) f1 = base + __ffs(m1) - 1;
            int p0 = cnt0 + __popc(m0 & lt);
            int p1 = cnt1 + __popc(m1 & lt);
            if (ok0 && p0 < 32) out0[p0] = i;
            if (ok1 && p1 < 64) out1[p1] = i;
            cnt0 = min(32, cnt0 + __popc(m0));
            cnt1 = min(64, cnt1 + __popc(m1));
        }
        for (; base < NN && cnt0 < 32; base += 32) {
            int i = base + lane;
            float dx = sx[i]-cx, dy = sy[i]-cy, dz = sz[i]-cz;
            float d = __fadd_rn(__fadd_rn(__fmul_rn(dx,dx), __fmul_rn(dy,dy)), __fmul_rn(dz,dz));
            bool ok0 = d < r2a;
            unsigned m0 = __ballot_sync(0xffffffffu, ok0);
            if (f0 < 0 && m0) f0 = base + __ffs(m0) - 1;
            int p0 = cnt0 + __popc(m0 & lt);
            if (ok0 && p0 < 32) out0[p0] = i;
            cnt0 = min(32, cnt0 + __popc(m0));
        }
        for (int p = cnt0 + lane; p < 32; p += 32) out0[p] = f0;
        for (int p = cnt1 + lane; p < 64; p += 32) out1[p] = f1;
    }
}

// ---------------- tensor-core conv: 256 pos x COUTB, single fp16 x single fp16 ----------------
template<bool GATHER, bool POOL, int COUTB, int CPAD, int KP>
__global__ __launch_bounds__(256, 2) void conv_mma(
    const __half* __restrict__ xin,
    const uint16_t* __restrict__ Wh,
    const float* __restrict__ bias,
    const float* __restrict__ bns, const float* __restrict__ bnt,
    __half* __restrict__ y, float* __restrict__ ps, float* __restrict__ ps2,
    float* __restrict__ pmax, float* __restrict__ pmin,
    int cstride,
    const float* __restrict__ pc, const __half* __restrict__ fth,
    const float* __restrict__ newpc, const int* __restrict__ gidx,
    int mkshift, int kshift)
{
    constexpr int NK = CPAD/16;
    constexpr int WSTR = CPAD*2 + 16;
    constexpr int XROW = 48, XPLANE = 256*XROW;
    constexpr int WOFF = 2*XPLANE;
    constexpr int MOFF = WOFF + COUTB*WSTR;

    extern __shared__ __align__(16) unsigned char smem[];
    __half2* ss2 = (__half2*)(smem + MOFF);
    __half2* st2 = (__half2*)(smem + MOFF + 512);
    unsigned* sfb = (unsigned*)(smem + MOFF + 1024);
    float* sdx = (float*)(smem + MOFF + 2048);
    float* sdy = (float*)(smem + MOFF + 3072);
    float* sdz = (float*)(smem + MOFF + 4096);
    float* sm1 = (float*)(smem + MOFF + 5120);
    float* sm2 = sm1 + 8*COUTB;
    float* pmx = sm2 + 8*COUTB;
    float* pmn = pmx + 8*COUTB;

    const int tid = threadIdx.x, lane = tid & 31, w = tid >> 5;
    const int pblock = blockIdx.x * 256;
    const int ocbase = blockIdx.y * COUTB;
    const int nblk = gridDim.x;
    const uint16_t* Wh_b = Wh + (size_t)ocbase*CPAD;

    if (GATHER) {
        int p = pblock + tid;
        int bbv = p >> mkshift, mmv = (p >> kshift) & (MM-1);
        int ix = gidx[p];
        sfb[tid] = (unsigned)((bbv*NN + ix) * 64);
        sdx[tid] = pc[(size_t)(bbv*3+0)*NN+ix] - newpc[(size_t)(bbv*3+0)*MM+mmv];
        sdy[tid] = pc[(size_t)(bbv*3+1)*NN+ix] - newpc[(size_t)(bbv*3+1)*MM+mmv];
        sdz[tid] = pc[(size_t)(bbv*3+2)*NN+ix] - newpc[(size_t)(bbv*3+2)*MM+mmv];
    } else {
        if (tid < CPAD/2) {
            ss2[tid] = __floats2half2_rn(bns[2*tid], bns[2*tid+1]);
            st2[tid] = __floats2half2_rn(bnt[2*tid], bnt[2*tid+1]);
        }
    }
    for (int e = tid; e < COUTB*CPAD/2; e += 256) {
        int o = e / (CPAD/2), cp = e - o*(CPAD/2);
        *(uint32_t*)(smem + WOFF + o*WSTR + cp*4) = ((const uint32_t*)Wh_b)[e];
    }
    __syncthreads();

    uint2 hr[4];
    auto stage_load = [&](int kc) {
#pragma unroll
        for (int i = 0; i < 4; i++) {
            int e = tid + i*256, pos = e >> 2, c4 = e & 3;
            if (GATHER) {
                if (kc < 4) hr[i] = *(const uint2*)&fth[sfb[pos] + kc*16 + c4*4];
            } else {
                hr[i] = *(const uint2*)&xin[(size_t)(pblock+pos)*CPAD + kc*16 + c4*4];
            }
        }
    };
    auto stage_conv = [&](int kc, int buf) {
        unsigned char* xh = smem + buf*XPLANE;
#pragma unroll
        for (int i = 0; i < 4; i++) {
            int e = tid + i*256, pos = e >> 2, c4 = e & 3;
            uint2 o2v;
            if (GATHER) {
                if (kc < 4) o2v = hr[i];
                else if (c4 == 0) {
                    __half2 a = __floats2half2_rn(sdx[pos], sdy[pos]);
                    __half2 b = __floats2half2_rn(sdz[pos], 0.f);
                    o2v = make_uint2(*(uint32_t*)&a, *(uint32_t*)&b);
                } else o2v = make_uint2(0u, 0u);
            } else {
                int h0 = (kc*16 + c4*4) >> 1;
                __half2 v0 = *(__half2*)&hr[i].x;
                __half2 v1 = *(__half2*)&hr[i].y;
                v0 = __hfma2_relu(v0, ss2[h0],   st2[h0]);
                v1 = __hfma2_relu(v1, ss2[h0+1], st2[h0+1]);
                o2v = make_uint2(*(uint32_t*)&v0, *(uint32_t*)&v1);
            }
            *(uint2*)(xh + pos*XROW + c4*8) = o2v;
        }
    };

    const uint32_t base = smem_u32(smem);
    const uint32_t aoff = base + (uint32_t)((w*32 + (lane & 15))*XROW + (lane >> 4)*16);
    const uint32_t boff = base + WOFF +
        (uint32_t)((((lane >> 4) & 1)*8 + (lane & 7))*WSTR + ((lane >> 3) & 1)*16);

    float acc[2][COUTB/8][4];
#pragma unroll
    for (int t = 0; t < 2; t++)
#pragma unroll
        for (int n = 0; n < COUTB/8; n++)
#pragma unroll
            for (int c = 0; c < 4; c++) acc[t][n][c] = 0.f;

    stage_load(0); stage_conv(0, 0);
    __syncthreads();

    for (int kc = 0; kc < NK; kc++) {
        int buf = kc & 1;
        if (kc + 1 < NK) stage_load(kc + 1);
        uint32_t ah[2][4], bh[COUTB/16][4];
#pragma unroll
        for (int t = 0; t < 2; t++)
            LDSMX4(ah[t], aoff + t*16*XROW + buf*XPLANE);
#pragma unroll
        for (int j = 0; j < COUTB/16; j++)
            LDSMX4(bh[j], boff + j*16*WSTR + kc*32);
#pragma unroll
        for (int j = 0; j < COUTB/16; j++)
#pragma unroll
            for (int t = 0; t < 2; t++) {
                MMAH(acc[t][2*j],   ah[t], bh[j][0], bh[j][1]);
                MMAH(acc[t][2*j+1], ah[t], bh[j][2], bh[j][3]);
            }
        if (kc + 1 < NK) stage_conv(kc + 1, buf ^ 1);
        __syncthreads();
    }

    const int q = lane >> 2, r2i = (lane & 3)*2;
#pragma unroll
    for (int nt = 0; nt < COUTB/8; nt++) {
        int ocl = nt*8 + r2i;
        int oc  = ocbase + ocl;
        float2 bv = *(const float2*)&bias[oc];
        float s1x = 0.f, s1y = 0.f, s2x = 0.f, s2y = 0.f;
        float mxx = -1e30f, mxy = -1e30f, mnx = 1e30f, mny = 1e30f;
#pragma unroll
        for (int t = 0; t < 2; t++) {
            float2 c01 = make_float2(acc[t][nt][0]+bv.x, acc[t][nt][1]+bv.y);
            float2 c23 = make_float2(acc[t][nt][2]+bv.x, acc[t][nt][3]+bv.y);
            if (!POOL) {
                __half2 h01 = __floats2half2_rn(c01.x, c01.y);
                __half2 h23 = __floats2half2_rn(c23.x, c23.y);
                *(__half2*)&y[(size_t)(pblock + w*32 + t*16 + q)*cstride + oc]     = h01;
                *(__half2*)&y[(size_t)(pblock + w*32 + t*16 + q + 8)*cstride + oc] = h23;
                c01 = __half22float2(h01);
                c23 = __half22float2(h23);
            }
            s1x += c01.x + c23.x;  s1y += c01.y + c23.y;
            s2x += c01.x*c01.x + c23.x*c23.x;
            s2y += c01.y*c01.y + c23.y*c23.y;
            mxx = fmaxf(mxx, fmaxf(c01.x, c23.x)); mxy = fmaxf(mxy, fmaxf(c01.y, c23.y));
            mnx = fminf(mnx, fminf(c01.x, c23.x)); mny = fminf(mny, fminf(c01.y, c23.y));
        }
#pragma unroll
        for (int o2 = 4; o2 <= 16; o2 <<= 1) {
            s1x += __shfl_xor_sync(0xffffffffu, s1x, o2);
            s1y += __shfl_xor_sync(0xffffffffu, s1y, o2);
            s2x += __shfl_xor_sync(0xffffffffu, s2x, o2);
            s2y += __shfl_xor_sync(0xffffffffu, s2y, o2);
            if (POOL) {
                mxx = fmaxf(mxx, __shfl_xor_sync(0xffffffffu, mxx, o2));
                mxy = fmaxf(mxy, __shfl_xor_sync(0xffffffffu, mxy, o2));
                mnx = fminf(mnx, __shfl_xor_sync(0xffffffffu, mnx, o2));
                mny = fminf(mny, __shfl_xor_sync(0xffffffffu, mny, o2));
            }
        }
        if (q == 0) {
            sm1[w*COUTB + ocl] = s1x; sm1[w*COUTB + ocl + 1] = s1y;
            sm2[w*COUTB + ocl] = s2x; sm2[w*COUTB + ocl + 1] = s2y;
            if (POOL) {
                if (KP == 32) {
                    size_t g = (size_t)(pblock >> 5) + w;
                    pmax[(size_t)oc*GCOUNT + g] = mxx; pmax[(size_t)(oc+1)*GCOUNT + g] = mxy;
                    pmin[(size_t)oc*GCOUNT + g] = mnx; pmin[(size_t)(oc+1)*GCOUNT + g] = mny;
                } else {
                    pmx[w*COUTB + ocl] = mxx; pmx[w*COUTB + ocl + 1] = mxy;
                    pmn[w*COUTB + ocl] = mnx; pmn[w*COUTB + ocl + 1] = mny;
                }
            }
        }
    }
    __syncthreads();
    for (int e = tid; e < COUTB; e += 256) {
        float a = 0.f, b2 = 0.f;
#pragma unroll
        for (int wi = 0; wi < 8; wi++) { a += sm1[wi*COUTB + e]; b2 += sm2[wi*COUTB + e]; }
        ps [(size_t)(ocbase + e)*nblk + blockIdx.x] = a;
        ps2[(size_t)(ocbase + e)*nblk + blockIdx.x] = b2;
    }
    if (POOL && KP == 64) {
        for (int e = tid; e < COUTB*4; e += 256) {
            int g = e / COUTB, ocl = e - g*COUTB;
            float mx = fmaxf(pmx[(g*2)*COUTB + ocl], pmx[(g*2+1)*COUTB + ocl]);
            float mn = fminf(pmn[(g*2)*COUTB + ocl], pmn[(g*2+1)*COUTB + ocl]);
            size_t gg = (size_t)(pblock >> 6) + g;
            pmax[(size_t)(ocbase + ocl)*GCOUNT + gg] = mx;
            pmin[(size_t)(ocbase + ocl)*GCOUNT + gg] = mn;
        }
    }
}

// ---------------- finalize BN ----------------
__global__ __launch_bounds__(256) void finalize_kernel(const float* __restrict__ ps,
    const float* __restrict__ ps2, int nblk, float invP,
    const float* __restrict__ gamma, const float* __restrict__ beta,
    float* __restrict__ s, float* __restrict__ t)
{
    int c = blockIdx.x;
    float a = 0.f, b = 0.f;
    for (int i = threadIdx.x; i < nblk; i += 256) {
        a += ps [(size_t)c*nblk + i];
        b += ps2[(size_t)c*nblk + i];
    }
#pragma unroll
    for (int off = 16; off > 0; off >>= 1) {
        a += __shfl_down_sync(0xffffffffu, a, off);
        b += __shfl_down_sync(0xffffffffu, b, off);
    }
    __shared__ float sa[8], sb[8];
    int lane = threadIdx.x & 31, w = threadIdx.x >> 5;
    if (lane == 0) { sa[w] = a; sb[w] = b; }
    __syncthreads();
    if (threadIdx.x < 8) {
        a = sa[threadIdx.x]; b = sb[threadIdx.x];
#pragma unroll
        for (int off = 4; off > 0; off >>= 1) {
            a += __shfl_down_sync(0xffu, a, off);
            b += __shfl_down_sync(0xffu, b, off);
        }
        if (threadIdx.x == 0) {
            float mu = a * invP;
            float var = b * invP - mu*mu;
            float sc = gamma[c] / sqrtf(var + 1e-5f);
            s[c] = sc;
            t[c] = beta[c] - mu * sc;
        }
    }
}

// ---------------- pool apply ----------------
__global__ __launch_bounds__(256) void pool_apply_kernel(const float* __restrict__ pmax,
    const float* __restrict__ pmin, const float* __restrict__ s, const float* __restrict__ t,
    float* __restrict__ out, int chbase)
{
    int gid = blockIdx.x*256 + threadIdx.x;
    int oc = gid >> 14, g = gid & 16383;
    float sc = s[oc], tc = t[oc];
    float v = (sc > 0.f) ? pmax[gid] : pmin[gid];
    float r = fmaxf(v*sc + tc, 0.f);
    out[OUT_OFS + ((size_t)((g >> 10)*256 + chbase + oc))*MM + (g & 1023)] = r;
}

// ---------------- host ----------------
extern "C" void kernel_launch(void* const* d_in, const int* in_sizes, int n_in,
                              void* d_out, int out_size)
{
    const float* pc   = (const float*)d_in[0];
    const float* feat = (const float*)d_in[1];
    const float *bp[6], *gp[6], *bep[6];
    WPtrs wargs;
    for (int i = 0; i < 6; i++) {
        wargs.w[i] = (const float*)d_in[2 + 4*i];
        bp[i]  = (const float*)d_in[3 + 4*i];
        gp[i]  = (const float*)d_in[4 + 4*i];
        bep[i] = (const float*)d_in[5 + 4*i];
    }
    float* out = (float*)d_out;

    int *samp, *idx0, *idx1;
    float *sv, *tv, *ps, *ps2, *pmax, *pmin;
    __half *bufA, *bufB, *fth;
    uint16_t *wth;
    cudaGetSymbolAddress((void**)&samp, g_samp);
    cudaGetSymbolAddress((void**)&idx0, g_idx0);
    cudaGetSymbolAddress((void**)&idx1, g_idx1);
    cudaGetSymbolAddress((void**)&bufA, g_bufA);
    cudaGetSymbolAddress((void**)&bufB, g_bufB);
    cudaGetSymbolAddress((void**)&fth,  g_fth);
    cudaGetSymbolAddress((void**)&sv,   g_s);
    cudaGetSymbolAddress((void**)&tv,   g_t);
    cudaGetSymbolAddress((void**)&ps,   g_ps);
    cudaGetSymbolAddress((void**)&ps2,  g_ps2);
    cudaGetSymbolAddress((void**)&pmax, g_pmax);
    cudaGetSymbolAddress((void**)&pmin, g_pmin);
    cudaGetSymbolAddress((void**)&wth,  g_wth);

    // smem: 24576 (X db) + COUTB*WSTR (W) + 5120 + 32*COUTB*4
    const int sm_A = 24576 + 64*176 + 5120 + 8192;   // gather 64x80 = 49152
    const int sm_B = 24576 + 64*144 + 5120 + 8192;   // 64x64        = 47104
    const int sm_D = 24576 + 48*144 + 5120 + 6144;   // 48x64        = 42752
    const int sm_E = 24576 + 64*208 + 5120 + 8192;   // 64x96 pool   = 51200
    cudaFuncSetAttribute(conv_mma<true,false,64,80,32>,  cudaFuncAttributeMaxDynamicSharedMemorySize, sm_A);
    cudaFuncSetAttribute(conv_mma<false,false,64,64,32>, cudaFuncAttributeMaxDynamicSharedMemorySize, sm_B);
    cudaFuncSetAttribute(conv_mma<false,true,64,64,32>,  cudaFuncAttributeMaxDynamicSharedMemorySize, sm_B);
    cudaFuncSetAttribute(conv_mma<false,false,48,64,32>, cudaFuncAttributeMaxDynamicSharedMemorySize, sm_D);
    cudaFuncSetAttribute(conv_mma<false,true,64,96,64>,  cudaFuncAttributeMaxDynamicSharedMemorySize, sm_E);

    ftr_kernel<<<dim3(128, 2, BB), dim3(32, 8)>>>(feat, fth);
    fps_kernel<<<BB + 6, 512>>>(pc, samp, out, wargs, wth);
    ballquery2_kernel<<<dim3(BB,32), 256, 3*NN*sizeof(float)>>>(pc, samp, idx0, idx1, 0.01f, 0.04f);

    const int nb0 = P0/256, nb1 = P1/256;

    // branch 1 first (bigger): 67->64->96->128, K=64
    conv_mma<true,false,64,80,32><<<dim3(nb1,1), 256, sm_A>>>(nullptr, wth+3*12288,
        bp[3], nullptr, nullptr, bufA, ps, ps2, nullptr, nullptr, 64, pc, fth, out, idx1, 16, 6);
    finalize_kernel<<<64, 256>>>(ps, ps2, nb1, 1.f/P1, gp[3], bep[3], sv, tv);
    conv_mma<false,false,48,64,32><<<dim3(nb1,2), 256, sm_D>>>(bufA, wth+4*12288,
        bp[4], sv, tv, bufB, ps, ps2, nullptr, nullptr, 96, nullptr, nullptr, nullptr, nullptr, 0, 0);
    finalize_kernel<<<96, 256>>>(ps, ps2, nb1, 1.f/P1, gp[4], bep[4], sv, tv);
    conv_mma<false,true,64,96,64><<<dim3(nb1,2), 256, sm_E>>>(bufB, wth+5*12288,
        bp[5], sv, tv, nullptr, ps, ps2, pmax, pmin, 128, nullptr, nullptr, nullptr, nullptr, 0, 0);
    finalize_kernel<<<128, 256>>>(ps, ps2, nb1, 1.f/P1, gp[5], bep[5], sv, tv);
    pool_apply_kernel<<<(128*GCOUNT)/256, 256>>>(pmax, pmin, sv, tv, out, 128);

    // branch 0: 67->64->64->128, K=32
    conv_mma<true,false,64,80,32><<<dim3(nb0,1), 256, sm_A>>>(nullptr, wth+0*12288,
        bp[0], nullptr, nullptr, bufA, ps, ps2, nullptr, nullptr, 64, pc, fth, out, idx0, 15, 5);
    finalize_kernel<<<64, 256>>>(ps, ps2, nb0, 1.f/P0, gp[0], bep[0], sv, tv);
    conv_mma<false,false,64,64,32><<<dim3(nb0,1), 256, sm_B>>>(bufA, wth+1*12288,
        bp[1], sv, tv, bufB, ps, ps2, nullptr, nullptr, 64, nullptr, nullptr, nullptr, nullptr, 0, 0);
    finalize_kernel<<<64, 256>>>(ps, ps2, nb0, 1.f/P0, gp[1], bep[1], sv, tv);
    conv_mma<false,true,64,64,32><<<dim3(nb0,2), 256, sm_B>>>(bufB, wth+2*12288,
        bp[2], sv, tv, nullptr, ps, ps2, pmax, pmin, 128, nullptr, nullptr, nullptr, nullptr, 0, 0);
    finalize_kernel<<<128, 256>>>(ps, ps2, nb0, 1.f/P0, gp[2], bep[2], sv, tv);
    pool_apply_kernel<<<(128*GCOUNT)/256, 256>>>(pmax, pmin, sv, tv, out, 0);
}